// round 15
// baseline (speedup 1.0000x reference)
#include <cuda_runtime.h>
#include <cuda_bf16.h>
#include <cstddef>

#define RR   7
#define KS   15            // 2R+1
#define NK   (KS*KS)       // 225
#define BATCH 8
#define HI   512
#define WI   512
#define HO   256
#define WO   256
#define TY   4             // output rows per block
#define SW   (WO + 2*RR)   // 270 (x window with halo)
#define SWP  280           // padded smem row stride (multiple of 4 -> 16B rows)
#define NBLK (BATCH * (HO/TY) * KS)   // 8*64*15 = 7680
#define DYN_SMEM 46080     // caps occupancy at 4 CTAs/SM (4*46080=184KB <= 228KB)

__global__ __launch_bounds__(256)
void adj_equality_kernel(const float* __restrict__ in, float* __restrict__ out)
{
    extern __shared__ float nb[];   // uses nb[0 .. 4*SWP)

    // item decode: (dy, b, ytile) with SPATIAL index fastest ->
    // concurrent blocks sweep each dx-plane sequentially in y (page locality)
    const int item = blockIdx.x;
    const int sp   = item & 511;         // 0..511  (b,ytile) fastest
    const int dy   = item >> 9;          // 0..14
    const int yt   = sp & 63;            // 0..63
    const int b    = sp >> 6;            // 0..7
    const int y0   = yt * TY;

    const int tid = threadIdx.x;
    const int tx  = tid & 63;            // 0..63
    const int ty  = tid >> 6;            // 0..3
    const int lx  = tx * 4;

    const float* __restrict__ inb = in + (size_t)b * HI * WI;

    // ---- Fill: row group ty fills smem row ty, columns tx, tx+64, ... ----
    {
        const int ny = y0 + ty + dy - RR;
        const bool yok = (ny >= 0) && (ny < HO);
        const float* __restrict__ irow = inb + (size_t)(ny * 2) * WI;
        float* __restrict__ srow = nb + ty * SWP;
        #pragma unroll
        for (int k = 0; k < 5; ++k) {    // 5*64 = 320 >= 270
            const int c = tx + k * 64;
            if (c < SW) {
                const int gx = c - RR;
                float v = 0.0f;
                if (yok && gx >= 0 && gx < WO)
                    v = irow[(size_t)(gx * 2)];
                srow[c] = v;
            }
        }
    }

    // ---- Centers straight from global (L2-hot) ----
    const int y = y0 + ty;
    const float* __restrict__ crow = inb + (size_t)(y * 2) * WI;
    const float c0 = crow[(size_t)((lx + 0) * 2)];
    const float c1 = crow[(size_t)((lx + 1) * 2)];
    const float c2 = crow[(size_t)((lx + 2) * 2)];
    const float c3 = crow[(size_t)((lx + 3) * 2)];

    __syncthreads();

    // ---- Register window: 20 floats via 5x LDS.128 (16B-aligned, conflict-free) ----
    const float4* __restrict__ wrow =
        reinterpret_cast<const float4*>(nb + ty * SWP + lx);
    float w[20];
    #pragma unroll
    for (int q = 0; q < 5; ++q) {
        const float4 v = wrow[q];
        w[q * 4 + 0] = v.x;
        w[q * 4 + 1] = v.y;
        w[q * 4 + 2] = v.z;
        w[q * 4 + 3] = v.w;
    }

    float* __restrict__ outp = out + ((size_t)b * NK + (size_t)(dy * KS)) * HO * WO
                                   + (size_t)y * WO + lx;

    #pragma unroll
    for (int dx = 0; dx < KS; ++dx) {
        float4 v;
        v.x = (w[dx + 0] == c0) ? 1.0f : 0.0f;
        v.y = (w[dx + 1] == c1) ? 1.0f : 0.0f;
        v.z = (w[dx + 2] == c2) ? 1.0f : 0.0f;
        v.w = (w[dx + 3] == c3) ? 1.0f : 0.0f;
        // write-through store: skip L2 dirty-line lifecycle for the
        // never-re-read 472MB output stream
        __stwt(reinterpret_cast<float4*>(outp + (size_t)dx * HO * WO), v);
    }
}

extern "C" void kernel_launch(void* const* d_in, const int* in_sizes, int n_in,
                              void* d_out, int out_size)
{
    const float* segments = (const float*)d_in[0];
    float* out = (float*)d_out;

    adj_equality_kernel<<<NBLK, 256, DYN_SMEM>>>(segments, out);
}

// round 16
// speedup vs baseline: 1.0647x; 1.0647x over previous
#include <cuda_runtime.h>
#include <cuda_bf16.h>
#include <cstddef>

#define RR   7
#define KS   15            // 2R+1
#define NK   (KS*KS)       // 225
#define BATCH 8
#define HI   512
#define WI   512
#define HO   256
#define WO   256
#define TY   4             // output rows per block
#define SW   (WO + 2*RR)   // 270 (x window with halo)
#define SWP  280           // padded smem row stride (multiple of 4 -> 16B rows)
#define NBLK (BATCH * (HO/TY) * KS)   // 8*64*15 = 7680
#define DYN_SMEM 46080     // caps occupancy at 4 CTAs/SM (4*46080=184KB <= 228KB)

__global__ __launch_bounds__(256)
void adj_equality_kernel(const float* __restrict__ in, float* __restrict__ out)
{
    extern __shared__ float nb[];   // uses nb[0 .. 4*SWP)

    // item decode: (dy, b, ytile) with SPATIAL index fastest ->
    // concurrent blocks sweep each dx-plane sequentially in y (page locality)
    const int item = blockIdx.x;
    const int sp   = item & 511;         // 0..511  (b,ytile) fastest
    const int dy   = item >> 9;          // 0..14
    const int yt   = sp & 63;            // 0..63
    const int b    = sp >> 6;            // 0..7
    const int y0   = yt * TY;

    const int tid = threadIdx.x;
    const int tx  = tid & 63;            // 0..63
    const int ty  = tid >> 6;            // 0..3
    const int lx  = tx * 4;

    const float* __restrict__ inb = in + (size_t)b * HI * WI;

    // ---- Fill: row group ty fills smem row ty, columns tx, tx+64, ... ----
    {
        const int ny = y0 + ty + dy - RR;
        const bool yok = (ny >= 0) && (ny < HO);
        const float* __restrict__ irow = inb + (size_t)(ny * 2) * WI;
        float* __restrict__ srow = nb + ty * SWP;
        #pragma unroll
        for (int k = 0; k < 5; ++k) {    // 5*64 = 320 >= 270
            const int c = tx + k * 64;
            if (c < SW) {
                const int gx = c - RR;
                float v = 0.0f;
                if (yok && gx >= 0 && gx < WO)
                    v = irow[(size_t)(gx * 2)];
                srow[c] = v;
            }
        }
    }

    // ---- Centers straight from global (L2-hot) ----
    const int y = y0 + ty;
    const float* __restrict__ crow = inb + (size_t)(y * 2) * WI;
    const float c0 = crow[(size_t)((lx + 0) * 2)];
    const float c1 = crow[(size_t)((lx + 1) * 2)];
    const float c2 = crow[(size_t)((lx + 2) * 2)];
    const float c3 = crow[(size_t)((lx + 3) * 2)];

    __syncthreads();

    // ---- Register window: 20 floats via 5x LDS.128 (16B-aligned, conflict-free) ----
    const float4* __restrict__ wrow =
        reinterpret_cast<const float4*>(nb + ty * SWP + lx);
    float w[20];
    #pragma unroll
    for (int q = 0; q < 5; ++q) {
        const float4 v = wrow[q];
        w[q * 4 + 0] = v.x;
        w[q * 4 + 1] = v.y;
        w[q * 4 + 2] = v.z;
        w[q * 4 + 3] = v.w;
    }

    float* __restrict__ outp = out + ((size_t)b * NK + (size_t)(dy * KS)) * HO * WO
                                   + (size_t)y * WO + lx;

    #pragma unroll
    for (int dx = 0; dx < KS; ++dx) {
        float4 v;
        v.x = (w[dx + 0] == c0) ? 1.0f : 0.0f;
        v.y = (w[dx + 1] == c1) ? 1.0f : 0.0f;
        v.z = (w[dx + 2] == c2) ? 1.0f : 0.0f;
        v.w = (w[dx + 3] == c3) ? 1.0f : 0.0f;
        // streaming store hint: evict-first dirty lines -> steadier L2->DRAM drain
        __stcs(reinterpret_cast<float4*>(outp + (size_t)dx * HO * WO), v);
    }
}

extern "C" void kernel_launch(void* const* d_in, const int* in_sizes, int n_in,
                              void* d_out, int out_size)
{
    const float* segments = (const float*)d_in[0];
    float* out = (float*)d_out;

    adj_equality_kernel<<<NBLK, 256, DYN_SMEM>>>(segments, out);
}